// round 13
// baseline (speedup 1.0000x reference)
#include <cuda_runtime.h>

#define EPS 0.1f
#define BB 64
#define II 1024
#define HH 4096
#define OO 256

__device__ float g_w1norm[HH];

// ---------------------------------------------------------------------------
// K1: W1_norm[j] = sum_i |W1[j,i]|  (R3-proven config)
//   512 blocks x 256 threads; one warp per row; 8 outstanding LDG.128/thread
// ---------------------------------------------------------------------------
__global__ void k_w1norm(const float* __restrict__ W1) {
    const int lid = threadIdx.x & 31;
    const int row = blockIdx.x * 8 + (threadIdx.x >> 5);
    const float4* r = reinterpret_cast<const float4*>(W1 + (size_t)row * II);
    float4 v[8];
    #pragma unroll
    for (int k = 0; k < 8; k++) v[k] = r[lid + k * 32];
    float s = 0.f;
    #pragma unroll
    for (int k = 0; k < 8; k++)
        s += fabsf(v[k].x) + fabsf(v[k].y) + fabsf(v[k].z) + fabsf(v[k].w);
    #pragma unroll
    for (int o = 16; o; o >>= 1) s += __shfl_down_sync(0xffffffffu, s, o);
    if (lid == 0) g_w1norm[row] = s;
}

// ---------------------------------------------------------------------------
// K2: fused nn_output + pert, grid = 256 + 512 = 768 blocks (SINGLE WAVE at
//     6 blocks/SM) x 256 threads.
//   bid <  256 : nn_output row i = bid (light; also warms W2 rows in L2)
//   bid >= 256 : pert DOUBLE unit p = bid-256: i = p>>1, half = p&1.
//                Thread owns TWO s float4s (chunks 2*half and 2*half+1);
//                streams 64 iterations x 2 STG.128 — no second wave, no tail.
// ---------------------------------------------------------------------------
__global__ void __launch_bounds__(256, 6)
k_main(const int* __restrict__ y,
       const float* __restrict__ W2,
       const float* __restrict__ bias2,
       float* __restrict__ out_nn,
       float* __restrict__ pert) {
    const int bid = blockIdx.x;
    const int lid = threadIdx.x & 31;
    const int wid = threadIdx.x >> 5;

    if (bid < 256) {
        // ---- nn_output row i ----
        const int i = bid;
        const float4* r = reinterpret_cast<const float4*>(W2 + (size_t)i * HH);
        float4 v[4];
        #pragma unroll
        for (int k = 0; k < 4; k++) v[k] = r[threadIdx.x + k * 256];
        float s = 0.f;
        #pragma unroll
        for (int k = 0; k < 4; k++) s += v[k].x + v[k].y + v[k].z + v[k].w;

        __shared__ float sm[8];
        #pragma unroll
        for (int o = 16; o; o >>= 1) s += __shfl_down_sync(0xffffffffu, s, o);
        if (lid == 0) sm[wid] = s;
        __syncthreads();
        __shared__ float total;
        if (threadIdx.x < 8) {
            float t = sm[threadIdx.x];
            #pragma unroll
            for (int o = 4; o; o >>= 1) t += __shfl_down_sync(0xffu, t, o);
            if (threadIdx.x == 0) total = t * (float)HH + bias2[i];
        }
        __syncthreads();
        if (threadIdx.x < BB)
            out_nn[(size_t)threadIdx.x * OO + i] = total;
        return;
    }

    // ---- pert: two chunks per block ----
    const int p    = bid - 256;          // 0..511
    const int i    = p >> 1;
    const int half = p & 1;
    const int j4a  = half * 512 + threadIdx.x;   // first chunk's float4 index
    const int j4b  = j4a + 256;                  // second chunk's float4 index

    __shared__ float yf[BB];
    if (threadIdx.x < BB) yf[threadIdx.x] = (float)y[(size_t)threadIdx.x * OO + i];
    __syncthreads();

    const float4* w2row = reinterpret_cast<const float4*>(W2 + (size_t)i * HH);
    const float4* nrm   = reinterpret_cast<const float4*>(g_w1norm);
    float4 wa = w2row[j4a], wb = w2row[j4b];
    float4 na = nrm[j4a],   nb = nrm[j4b];

    float4 sa, sb;
    sa.x = -EPS * ((wa.x > 0.f) ? 1.f : (wa.x < 0.f) ? -1.f : 0.f) * na.x;
    sa.y = -EPS * ((wa.y > 0.f) ? 1.f : (wa.y < 0.f) ? -1.f : 0.f) * na.y;
    sa.z = -EPS * ((wa.z > 0.f) ? 1.f : (wa.z < 0.f) ? -1.f : 0.f) * na.z;
    sa.w = -EPS * ((wa.w > 0.f) ? 1.f : (wa.w < 0.f) ? -1.f : 0.f) * na.w;
    sb.x = -EPS * ((wb.x > 0.f) ? 1.f : (wb.x < 0.f) ? -1.f : 0.f) * nb.x;
    sb.y = -EPS * ((wb.y > 0.f) ? 1.f : (wb.y < 0.f) ? -1.f : 0.f) * nb.y;
    sb.z = -EPS * ((wb.z > 0.f) ? 1.f : (wb.z < 0.f) ? -1.f : 0.f) * nb.z;
    sb.w = -EPS * ((wb.w > 0.f) ? 1.f : (wb.w < 0.f) ? -1.f : 0.f) * nb.w;

    float* basea = pert + (size_t)i * HH + (size_t)j4a * 4;
    float* baseb = pert + (size_t)i * HH + (size_t)j4b * 4;
    #pragma unroll 4
    for (int b = 0; b < BB; b++) {
        const size_t off = (size_t)b * OO * HH;
        float yb = yf[b];
        float4 oa, ob;
        oa.x = yb * sa.x; oa.y = yb * sa.y; oa.z = yb * sa.z; oa.w = yb * sa.w;
        ob.x = yb * sb.x; ob.y = yb * sb.y; ob.z = yb * sb.z; ob.w = yb * sb.w;
        __stcs(reinterpret_cast<float4*>(basea + off), oa);
        __stcs(reinterpret_cast<float4*>(baseb + off), ob);
    }
}

// ---------------------------------------------------------------------------
// launch
// inputs: x[0] (unused), y[1], W1[2], W2[3], bias1[4] (unused), bias2[5]
// out layout: nn_output [B*O] then pert [B*O*H]
// ---------------------------------------------------------------------------
extern "C" void kernel_launch(void* const* d_in, const int* in_sizes, int n_in,
                              void* d_out, int out_size) {
    const int*   y     = (const int*)d_in[1];
    const float* W1    = (const float*)d_in[2];
    const float* W2    = (const float*)d_in[3];
    const float* bias2 = (const float*)d_in[5];

    float* out_nn = (float*)d_out;
    float* pert   = out_nn + (size_t)BB * OO;

    k_w1norm<<<512, 256>>>(W1);
    k_main<<<256 + 512, 256>>>(y, W2, bias2, out_nn, pert);
}

// round 14
// speedup vs baseline: 1.1229x; 1.1229x over previous
#include <cuda_runtime.h>

#define EPS 0.1f
#define BB 64
#define II 1024
#define HH 4096
#define OO 256

__device__ float g_w1norm[HH];

// ---------------------------------------------------------------------------
// K1: W1_norm[j] = sum_i |W1[j,i]|
//   592 blocks (=148 SMs x 4, placement-balanced single wave) x 256 threads;
//   one warp per row (8 outstanding LDG.128/thread), rows >= 4096 guarded.
// ---------------------------------------------------------------------------
__global__ void k_w1norm(const float* __restrict__ W1) {
    const int lid = threadIdx.x & 31;
    const int row = blockIdx.x * 8 + (threadIdx.x >> 5);
    if (row >= HH) return;
    const float4* r = reinterpret_cast<const float4*>(W1 + (size_t)row * II);
    float4 v[8];
    #pragma unroll
    for (int k = 0; k < 8; k++) v[k] = r[lid + k * 32];
    float s = 0.f;
    #pragma unroll
    for (int k = 0; k < 8; k++)
        s += fabsf(v[k].x) + fabsf(v[k].y) + fabsf(v[k].z) + fabsf(v[k].w);
    #pragma unroll
    for (int o = 16; o; o >>= 1) s += __shfl_down_sync(0xffffffffu, s, o);
    if (lid == 0) g_w1norm[row] = s;
}

// ---------------------------------------------------------------------------
// K2: fused nn_output + pert — R3 structure (best measured, 45.57us).
//   grid = 256 + 1024 blocks, 256 threads.
//   bid <  256 : nn_output row i = bid
//   bid >= 256 : pert unit p = bid-256 (i = p>>2, chunk = p&3);
//                one s float4 per thread, 64 STG.128 (.cs), unroll 16.
// ---------------------------------------------------------------------------
__global__ void k_main(const int* __restrict__ y,
                       const float* __restrict__ W2,
                       const float* __restrict__ bias2,
                       float* __restrict__ out_nn,
                       float* __restrict__ pert) {
    const int bid = blockIdx.x;
    const int lid = threadIdx.x & 31;
    const int wid = threadIdx.x >> 5;

    if (bid < 256) {
        // ---- nn_output row i ----
        const int i = bid;
        const float4* r = reinterpret_cast<const float4*>(W2 + (size_t)i * HH);
        float4 v[4];
        #pragma unroll
        for (int k = 0; k < 4; k++) v[k] = r[threadIdx.x + k * 256];
        float s = 0.f;
        #pragma unroll
        for (int k = 0; k < 4; k++) s += v[k].x + v[k].y + v[k].z + v[k].w;

        __shared__ float sm[8];
        #pragma unroll
        for (int o = 16; o; o >>= 1) s += __shfl_down_sync(0xffffffffu, s, o);
        if (lid == 0) sm[wid] = s;
        __syncthreads();
        __shared__ float total;
        if (threadIdx.x < 8) {
            float t = sm[threadIdx.x];
            #pragma unroll
            for (int o = 4; o; o >>= 1) t += __shfl_down_sync(0xffu, t, o);
            if (threadIdx.x == 0) total = t * (float)HH + bias2[i];
        }
        __syncthreads();
        if (threadIdx.x < BB)
            out_nn[(size_t)threadIdx.x * OO + i] = total;
        return;
    }

    // ---- pert ----
    const int p  = bid - 256;
    const int i  = p >> 2;
    const int j4 = (p & 3) * 256 + threadIdx.x;

    __shared__ float yf[BB];
    if (threadIdx.x < BB) yf[threadIdx.x] = (float)y[(size_t)threadIdx.x * OO + i];
    __syncthreads();

    float4 w = reinterpret_cast<const float4*>(W2 + (size_t)i * HH)[j4];
    float4 n = reinterpret_cast<const float4*>(g_w1norm)[j4];
    float4 s;
    s.x = -EPS * ((w.x > 0.f) ? 1.f : (w.x < 0.f) ? -1.f : 0.f) * n.x;
    s.y = -EPS * ((w.y > 0.f) ? 1.f : (w.y < 0.f) ? -1.f : 0.f) * n.y;
    s.z = -EPS * ((w.z > 0.f) ? 1.f : (w.z < 0.f) ? -1.f : 0.f) * n.z;
    s.w = -EPS * ((w.w > 0.f) ? 1.f : (w.w < 0.f) ? -1.f : 0.f) * n.w;

    float* base = pert + (size_t)i * HH + (size_t)j4 * 4;
    #pragma unroll 16
    for (int b = 0; b < BB; b++) {
        float yb = yf[b];
        float4 o;
        o.x = yb * s.x; o.y = yb * s.y; o.z = yb * s.z; o.w = yb * s.w;
        __stcs(reinterpret_cast<float4*>(base + (size_t)b * OO * HH), o);
    }
}

// ---------------------------------------------------------------------------
// launch
// inputs: x[0] (unused), y[1], W1[2], W2[3], bias1[4] (unused), bias2[5]
// out layout: nn_output [B*O] then pert [B*O*H]
// ---------------------------------------------------------------------------
extern "C" void kernel_launch(void* const* d_in, const int* in_sizes, int n_in,
                              void* d_out, int out_size) {
    const int*   y     = (const int*)d_in[1];
    const float* W1    = (const float*)d_in[2];
    const float* W2    = (const float*)d_in[3];
    const float* bias2 = (const float*)d_in[5];

    float* out_nn = (float*)d_out;
    float* pert   = out_nn + (size_t)BB * OO;

    k_w1norm<<<592, 256>>>(W1);
    k_main<<<256 + 1024, 256>>>(y, W2, bias2, out_nn, pert);
}